// round 13
// baseline (speedup 1.0000x reference)
#include <cuda_runtime.h>
#include <cuda_bf16.h>
#include <stdint.h>

#define SEQ 2048
#define DH  128
#define NBH 64
#define BM  128
#define BN  32
#define QTILES (SEQ/BM)       // 16
#define STR 136               // padded smem row stride in bf16 elems (17x16B -> conflict-free)

__device__ float g_rls[NBH * SEQ];

// smem element offsets (bf16 units)
#define E_QHI 0
#define E_QLO (E_QHI + BM*STR)        // 17408
#define E_KV0 (2*BM*STR)              // 34816  (two ping-pong K/V buffers follow)
#define KVBUF (4*BN*STR)              // 17408 elems per buffer
#define O_KHI 0
#define O_KLO (BN*STR)
#define O_VHI (2*BN*STR)
#define O_VLO (3*BN*STR)
#define SM_ELEMS (E_KV0 + 2*KVBUF)    // 69632
#define SM_BYTES (SM_ELEMS * 2)       // 139264

__device__ __forceinline__ uint32_t smem_u32(const void* p) {
    uint32_t a;
    asm("{ .reg .u64 t; cvta.to.shared.u64 t, %1; cvt.u32.u64 %0, t; }"
        : "=r"(a) : "l"(p));
    return a;
}
__device__ __forceinline__ void ldsm4(uint32_t r[4], uint32_t addr) {
    asm volatile("ldmatrix.sync.aligned.m8n8.x4.shared.b16 {%0,%1,%2,%3}, [%4];"
                 : "=r"(r[0]), "=r"(r[1]), "=r"(r[2]), "=r"(r[3]) : "r"(addr));
}
__device__ __forceinline__ void ldsm4t(uint32_t r[4], uint32_t addr) {
    asm volatile("ldmatrix.sync.aligned.m8n8.x4.trans.shared.b16 {%0,%1,%2,%3}, [%4];"
                 : "=r"(r[0]), "=r"(r[1]), "=r"(r[2]), "=r"(r[3]) : "r"(addr));
}
__device__ __forceinline__ void mma16816(float c[4], const uint32_t a[4],
                                         uint32_t b0, uint32_t b1) {
    asm volatile("mma.sync.aligned.m16n8k16.row.col.f32.bf16.bf16.f32 "
                 "{%0,%1,%2,%3},{%4,%5,%6,%7},{%8,%9},{%0,%1,%2,%3};"
                 : "+f"(c[0]), "+f"(c[1]), "+f"(c[2]), "+f"(c[3])
                 : "r"(a[0]), "r"(a[1]), "r"(a[2]), "r"(a[3]), "r"(b0), "r"(b1));
}
__device__ __forceinline__ uint32_t bpackf(float x, float y) {
    __nv_bfloat16 a = __float2bfloat16_rn(x), b = __float2bfloat16_rn(y);
    return ((uint32_t)__bfloat16_as_ushort(b) << 16) | (uint32_t)__bfloat16_as_ushort(a);
}
__device__ __forceinline__ uint32_t bpackres(float x, float y) {
    __nv_bfloat16 a = __float2bfloat16_rn(x), b = __float2bfloat16_rn(y);
    float xr = x - __bfloat162float(a), yr = y - __bfloat162float(b);
    __nv_bfloat16 ar = __float2bfloat16_rn(xr), br = __float2bfloat16_rn(yr);
    return ((uint32_t)__bfloat16_as_ushort(br) << 16) | (uint32_t)__bfloat16_as_ushort(ar);
}
__device__ __forceinline__ void split4_store(__nv_bfloat16* hi, __nv_bfloat16* lo,
                                             int off, float4 v) {
    __nv_bfloat16 h0 = __float2bfloat16_rn(v.x), h1 = __float2bfloat16_rn(v.y);
    __nv_bfloat16 h2 = __float2bfloat16_rn(v.z), h3 = __float2bfloat16_rn(v.w);
    __nv_bfloat16 l0 = __float2bfloat16_rn(v.x - __bfloat162float(h0));
    __nv_bfloat16 l1 = __float2bfloat16_rn(v.y - __bfloat162float(h1));
    __nv_bfloat16 l2 = __float2bfloat16_rn(v.z - __bfloat162float(h2));
    __nv_bfloat16 l3 = __float2bfloat16_rn(v.w - __bfloat162float(h3));
    uint32_t ph0 = ((uint32_t)__bfloat16_as_ushort(h1) << 16) | __bfloat16_as_ushort(h0);
    uint32_t ph1 = ((uint32_t)__bfloat16_as_ushort(h3) << 16) | __bfloat16_as_ushort(h2);
    uint32_t pl0 = ((uint32_t)__bfloat16_as_ushort(l1) << 16) | __bfloat16_as_ushort(l0);
    uint32_t pl1 = ((uint32_t)__bfloat16_as_ushort(l3) << 16) | __bfloat16_as_ushort(l2);
    *(uint2*)(hi + off) = make_uint2(ph0, ph1);
    *(uint2*)(lo + off) = make_uint2(pl0, pl1);
}

__global__ void __launch_bounds__(256)
attn_mma(const float* __restrict__ Q, const float* __restrict__ K,
         const float* __restrict__ V, float* __restrict__ W,
         float* __restrict__ Ctx)
{
    extern __shared__ __nv_bfloat16 sm[];
    const uint32_t sb = smem_u32(sm);
    const int tid  = threadIdx.x;
    const int wid  = tid >> 5;
    const int lane = tid & 31;
    const int qt   = (QTILES - 1) - blockIdx.x;    // heavy tiles first
    const int bh   = blockIdx.y;

    const size_t base = (size_t)bh * SEQ * DH;
    const float* Qb = Q + base + (size_t)qt * BM * DH;

    // per-thread K/V load coordinates (4 float4 per tensor)
    int ld_row[4], ld_c4[4];
    #pragma unroll
    for (int i = 0; i < 4; ++i) {
        int e = tid + i * 256;
        ld_row[i] = e >> 5;
        ld_c4[i]  = (e & 31) * 4;
    }

    // ---- Load Q tile -> smem hi/lo (padded rows) ----
    for (int e = tid; e < BM * DH / 4; e += 256) {
        int row = e >> 5, c4 = (e & 31) * 4;
        split4_store(sm + E_QHI, sm + E_QLO, row * STR + c4,
                     *(const float4*)&Qb[row * DH + c4]);
    }

    // ---- Preload K/V tile 0 into buffer 0 ----
    {
        const float* Kt = K + base;
        const float* Vt = V + base;
        #pragma unroll
        for (int i = 0; i < 4; ++i) {
            int off = ld_row[i] * STR + ld_c4[i];
            int g   = ld_row[i] * DH + ld_c4[i];
            split4_store(sm + E_KV0 + O_KHI, sm + E_KV0 + O_KLO, off,
                         *(const float4*)&Kt[g]);
            split4_store(sm + E_KV0 + O_VHI, sm + E_KV0 + O_VLO, off,
                         *(const float4*)&Vt[g]);
        }
    }

    // fragment row indices
    const int i0 = qt * BM + wid * 16 + (lane >> 2);
    const int i1 = i0 + 8;
    const int jq = (lane & 3) * 2;
    float* wrow0 = W ? W + ((size_t)bh * SEQ + i0) * SEQ : (float*)0;
    float* wrow1 = W ? W + ((size_t)bh * SEQ + i1) * SEQ : (float*)0;

    float o[16][4];
    #pragma unroll
    for (int n = 0; n < 16; ++n)
        #pragma unroll
        for (int r = 0; r < 4; ++r) o[n][r] = 0.0f;
    float rsum0 = 0.0f, rsum1 = 0.0f;
    const float SCALE = 0.08838834764831843f;

    const int lt = lane >> 3, lr = lane & 7;
    __syncthreads();

    const int nkt = 4 * qt + 4;
    for (int kt = 0; kt < nkt; ++kt) {
        const int cvb = E_KV0 + (kt & 1) * KVBUF;            // current buffer
        const int nvb = E_KV0 + ((kt + 1) & 1) * KVBUF;      // next buffer

        // ---- stage next K/V tile into registers (latency hidden by QK) ----
        float4 kst[4], vst[4];
        const bool have_next = (kt + 1 < nkt);
        if (have_next) {
            const float* Kt = K + base + (size_t)(kt + 1) * BN * DH;
            const float* Vt = V + base + (size_t)(kt + 1) * BN * DH;
            #pragma unroll
            for (int i = 0; i < 4; ++i) {
                int g = ld_row[i] * DH + ld_c4[i];
                kst[i] = *(const float4*)&Kt[g];
                vst[i] = *(const float4*)&Vt[g];
            }
        }

        // ---- QK: S[128x32] via 3-term bf16 emulation (reads cvb) ----
        float S[4][4];
        #pragma unroll
        for (int n = 0; n < 4; ++n)
            #pragma unroll
            for (int r = 0; r < 4; ++r) S[n][r] = 0.0f;

        #pragma unroll
        for (int ks = 0; ks < 8; ++ks) {
            const int k0 = ks * 16;
            uint32_t a_off = (uint32_t)((wid * 16 + (lt & 1) * 8 + lr) * STR
                                        + k0 + (lt >> 1) * 8);
            uint32_t ah[4], al[4];
            ldsm4(ah, sb + (E_QHI + a_off) * 2);
            ldsm4(al, sb + (E_QLO + a_off) * 2);
            #pragma unroll
            for (int p = 0; p < 2; ++p) {
                uint32_t b_off = (uint32_t)((p * 16 + (lt >> 1) * 8 + lr) * STR
                                            + k0 + (lt & 1) * 8);
                uint32_t bhr[4], blr[4];
                ldsm4(bhr, sb + (cvb + O_KHI + b_off) * 2);
                ldsm4(blr, sb + (cvb + O_KLO + b_off) * 2);
                mma16816(S[2*p],   ah, bhr[0], bhr[1]);
                mma16816(S[2*p],   ah, blr[0], blr[1]);
                mma16816(S[2*p],   al, bhr[0], bhr[1]);
                mma16816(S[2*p+1], ah, bhr[2], bhr[3]);
                mma16816(S[2*p+1], ah, blr[2], blr[3]);
                mma16816(S[2*p+1], al, bhr[2], bhr[3]);
            }
        }

        // ---- store staged tile into next buffer (frees staging regs) ----
        if (have_next) {
            #pragma unroll
            for (int i = 0; i < 4; ++i) {
                int off = ld_row[i] * STR + ld_c4[i];
                split4_store(sm + nvb + O_KHI, sm + nvb + O_KLO, off, kst[i]);
                split4_store(sm + nvb + O_VHI, sm + nvb + O_VLO, off, vst[i]);
            }
        }

        // ---- exp + causal mask + W store (unnormalized), in registers ----
        #pragma unroll
        for (int nf = 0; nf < 4; ++nf) {
            const int j0 = kt * BN + nf * 8 + jq;
            float p0 = (j0     <= i0) ? __expf(fmaf(S[nf][0], SCALE, -12.0f)) : 0.0f;
            float p1 = (j0 + 1 <= i0) ? __expf(fmaf(S[nf][1], SCALE, -12.0f)) : 0.0f;
            float p2 = (j0     <= i1) ? __expf(fmaf(S[nf][2], SCALE, -12.0f)) : 0.0f;
            float p3 = (j0 + 1 <= i1) ? __expf(fmaf(S[nf][3], SCALE, -12.0f)) : 0.0f;
            rsum0 += p0 + p1;
            rsum1 += p2 + p3;
            if (wrow0) {
                *(float2*)(wrow0 + j0) = make_float2(p0, p1);
                *(float2*)(wrow1 + j0) = make_float2(p2, p3);
            }
            S[nf][0] = p0; S[nf][1] = p1; S[nf][2] = p2; S[nf][3] = p3;
        }

        // ---- PV: O += P * V (3-term bf16 emulation, reads cvb) ----
        #pragma unroll
        for (int kk = 0; kk < 2; ++kk) {
            uint32_t pah[4], pal[4];
            pah[0] = bpackf(S[2*kk][0],   S[2*kk][1]);
            pah[1] = bpackf(S[2*kk][2],   S[2*kk][3]);
            pah[2] = bpackf(S[2*kk+1][0], S[2*kk+1][1]);
            pah[3] = bpackf(S[2*kk+1][2], S[2*kk+1][3]);
            pal[0] = bpackres(S[2*kk][0],   S[2*kk][1]);
            pal[1] = bpackres(S[2*kk][2],   S[2*kk][3]);
            pal[2] = bpackres(S[2*kk+1][0], S[2*kk+1][1]);
            pal[3] = bpackres(S[2*kk+1][2], S[2*kk+1][3]);
            #pragma unroll
            for (int np = 0; np < 8; ++np) {
                uint32_t v_off = (uint32_t)((kk * 16 + (lt & 1) * 8 + lr) * STR
                                            + np * 16 + (lt >> 1) * 8);
                uint32_t vh[4], vl[4];
                ldsm4t(vh, sb + (cvb + O_VHI + v_off) * 2);
                ldsm4t(vl, sb + (cvb + O_VLO + v_off) * 2);
                mma16816(o[2*np],   pah, vh[0], vh[1]);
                mma16816(o[2*np],   pah, vl[0], vl[1]);
                mma16816(o[2*np],   pal, vh[0], vh[1]);
                mma16816(o[2*np+1], pah, vh[2], vh[3]);
                mma16816(o[2*np+1], pah, vl[2], vl[3]);
                mma16816(o[2*np+1], pal, vh[2], vh[3]);
            }
        }

        __syncthreads();   // next-buf writes visible; current-buf reads done
    }

    // ---- row-sum reduce across quad lanes ----
    rsum0 += __shfl_xor_sync(0xffffffffu, rsum0, 1);
    rsum0 += __shfl_xor_sync(0xffffffffu, rsum0, 2);
    rsum1 += __shfl_xor_sync(0xffffffffu, rsum1, 1);
    rsum1 += __shfl_xor_sync(0xffffffffu, rsum1, 2);
    const float rinv0 = 1.0f / rsum0;
    const float rinv1 = 1.0f / rsum1;
    if ((lane & 3) == 0) {
        g_rls[bh * SEQ + i0] = rinv0;
        g_rls[bh * SEQ + i1] = rinv1;
    }

    // ---- context out ----
    if (Ctx) {
        float* c0 = Ctx + ((size_t)bh * SEQ + i0) * DH;
        float* c1 = Ctx + ((size_t)bh * SEQ + i1) * DH;
        #pragma unroll
        for (int nf = 0; nf < 16; ++nf) {
            const int cc = nf * 8 + jq;
            *(float2*)(c0 + cc) = make_float2(o[nf][0] * rinv0, o[nf][1] * rinv0);
            *(float2*)(c1 + cc) = make_float2(o[nf][2] * rinv1, o[nf][3] * rinv1);
        }
    }
}

// Pass 2: scale causal region by 1/rowsum, zero strictly-upper region.
__global__ void __launch_bounds__(256)
scale_w(float* __restrict__ Wt)
{
    const int row = blockIdx.x;
    const int bh  = blockIdx.y;
    const float rinv = g_rls[bh * SEQ + row];
    float* wr = Wt + ((size_t)bh * SEQ + row) * SEQ;

    int c0 = threadIdx.x * 4;
    #pragma unroll
    for (int it = 0; it < 2; ++it, c0 += 1024) {
        if (c0 > row) {
            *(float4*)&wr[c0] = make_float4(0.f, 0.f, 0.f, 0.f);
        } else {
            float4 w = *(const float4*)&wr[c0];
            w.x = w.x * rinv;
            w.y = (c0 + 1 <= row) ? w.y * rinv : 0.0f;
            w.z = (c0 + 2 <= row) ? w.z * rinv : 0.0f;
            w.w = (c0 + 3 <= row) ? w.w * rinv : 0.0f;
            *(float4*)&wr[c0] = w;
        }
    }
}

extern "C" void kernel_launch(void* const* d_in, const int* in_sizes, int n_in,
                              void* d_out, int out_size)
{
    const float* q = (const float*)d_in[0];
    const float* k = (const float*)d_in[1];
    const float* v = (const float*)d_in[2];

    const long long CTX_E = (long long)NBH * SEQ * DH;
    const long long W_E   = (long long)NBH * SEQ * SEQ;

    float* ctx = 0;
    float* w   = 0;
    const long long os = (long long)out_size;
    if (os == CTX_E + W_E)      { ctx = (float*)d_out; w = (float*)d_out + CTX_E; }
    else if (os == CTX_E)       { ctx = (float*)d_out; }
    else if (os == W_E)         { w   = (float*)d_out; }
    else                        { ctx = (float*)d_out; }

    cudaFuncSetAttribute(attn_mma,
                         cudaFuncAttributeMaxDynamicSharedMemorySize, SM_BYTES);

    dim3 grid1(QTILES, NBH);
    attn_mma<<<grid1, 256, SM_BYTES>>>(q, k, v, w, ctx);

    if (w) {
        dim3 grid2(SEQ, NBH);
        scale_w<<<grid2, 256>>>(w);
    }
}

// round 16
// speedup vs baseline: 1.0935x; 1.0935x over previous
#include <cuda_runtime.h>
#include <cuda_bf16.h>
#include <stdint.h>

#define SEQ 2048
#define DH  128
#define NBH 64
#define BM  64
#define BN  32
#define QTILES (SEQ/BM)       // 32
#define NT  128               // threads per CTA (4 warps)
#define STR 136               // padded smem row stride in bf16 elems (17x16B -> conflict-free)

__device__ float g_rls[NBH * SEQ];

// smem element offsets (bf16 units)
#define E_QHI 0
#define E_QLO (E_QHI + BM*STR)        // 8704
#define E_KHI (E_QLO + BM*STR)        // 17408
#define E_KLO (E_KHI + BN*STR)        // 21760
#define E_VHI (E_KLO + BN*STR)        // 26112
#define E_VLO (E_VHI + BN*STR)        // 30464
#define SM_ELEMS (E_VLO + BN*STR)     // 34816
#define SM_BYTES (SM_ELEMS * 2)       // 69632

__device__ __forceinline__ uint32_t smem_u32(const void* p) {
    uint32_t a;
    asm("{ .reg .u64 t; cvta.to.shared.u64 t, %1; cvt.u32.u64 %0, t; }"
        : "=r"(a) : "l"(p));
    return a;
}
__device__ __forceinline__ void ldsm4(uint32_t r[4], uint32_t addr) {
    asm volatile("ldmatrix.sync.aligned.m8n8.x4.shared.b16 {%0,%1,%2,%3}, [%4];"
                 : "=r"(r[0]), "=r"(r[1]), "=r"(r[2]), "=r"(r[3]) : "r"(addr));
}
__device__ __forceinline__ void ldsm4t(uint32_t r[4], uint32_t addr) {
    asm volatile("ldmatrix.sync.aligned.m8n8.x4.trans.shared.b16 {%0,%1,%2,%3}, [%4];"
                 : "=r"(r[0]), "=r"(r[1]), "=r"(r[2]), "=r"(r[3]) : "r"(addr));
}
__device__ __forceinline__ void mma16816(float c[4], const uint32_t a[4],
                                         uint32_t b0, uint32_t b1) {
    asm volatile("mma.sync.aligned.m16n8k16.row.col.f32.bf16.bf16.f32 "
                 "{%0,%1,%2,%3},{%4,%5,%6,%7},{%8,%9},{%0,%1,%2,%3};"
                 : "+f"(c[0]), "+f"(c[1]), "+f"(c[2]), "+f"(c[3])
                 : "r"(a[0]), "r"(a[1]), "r"(a[2]), "r"(a[3]), "r"(b0), "r"(b1));
}
__device__ __forceinline__ uint32_t bpackf(float x, float y) {
    __nv_bfloat16 a = __float2bfloat16_rn(x), b = __float2bfloat16_rn(y);
    return ((uint32_t)__bfloat16_as_ushort(b) << 16) | (uint32_t)__bfloat16_as_ushort(a);
}
__device__ __forceinline__ uint32_t bpackres(float x, float y) {
    __nv_bfloat16 a = __float2bfloat16_rn(x), b = __float2bfloat16_rn(y);
    float xr = x - __bfloat162float(a), yr = y - __bfloat162float(b);
    __nv_bfloat16 ar = __float2bfloat16_rn(xr), br = __float2bfloat16_rn(yr);
    return ((uint32_t)__bfloat16_as_ushort(br) << 16) | (uint32_t)__bfloat16_as_ushort(ar);
}
__device__ __forceinline__ void split4_store(__nv_bfloat16* hi, __nv_bfloat16* lo,
                                             int off, float4 v) {
    __nv_bfloat16 h0 = __float2bfloat16_rn(v.x), h1 = __float2bfloat16_rn(v.y);
    __nv_bfloat16 h2 = __float2bfloat16_rn(v.z), h3 = __float2bfloat16_rn(v.w);
    __nv_bfloat16 l0 = __float2bfloat16_rn(v.x - __bfloat162float(h0));
    __nv_bfloat16 l1 = __float2bfloat16_rn(v.y - __bfloat162float(h1));
    __nv_bfloat16 l2 = __float2bfloat16_rn(v.z - __bfloat162float(h2));
    __nv_bfloat16 l3 = __float2bfloat16_rn(v.w - __bfloat162float(h3));
    uint32_t ph0 = ((uint32_t)__bfloat16_as_ushort(h1) << 16) | __bfloat16_as_ushort(h0);
    uint32_t ph1 = ((uint32_t)__bfloat16_as_ushort(h3) << 16) | __bfloat16_as_ushort(h2);
    uint32_t pl0 = ((uint32_t)__bfloat16_as_ushort(l1) << 16) | __bfloat16_as_ushort(l0);
    uint32_t pl1 = ((uint32_t)__bfloat16_as_ushort(l3) << 16) | __bfloat16_as_ushort(l2);
    *(uint2*)(hi + off) = make_uint2(ph0, ph1);
    *(uint2*)(lo + off) = make_uint2(pl0, pl1);
}

__global__ void __launch_bounds__(NT, 3)
attn_mma(const float* __restrict__ Q, const float* __restrict__ K,
         const float* __restrict__ V, float* __restrict__ W,
         float* __restrict__ Ctx)
{
    extern __shared__ __nv_bfloat16 sm[];
    const uint32_t sb = smem_u32(sm);
    const int tid  = threadIdx.x;
    const int wid  = tid >> 5;
    const int lane = tid & 31;
    const int qt   = (QTILES - 1) - blockIdx.x;    // heavy tiles first
    const int bh   = blockIdx.y;

    const size_t base = (size_t)bh * SEQ * DH;
    const float* Qb = Q + base + (size_t)qt * BM * DH;

    // ---- Load Q tile -> smem hi/lo (padded rows) ----
    for (int e = tid; e < BM * DH / 4; e += NT) {
        int row = e >> 5, c4 = (e & 31) * 4;
        split4_store(sm + E_QHI, sm + E_QLO, row * STR + c4,
                     *(const float4*)&Qb[row * DH + c4]);
    }

    // fragment row indices
    const int i0 = qt * BM + wid * 16 + (lane >> 2);
    const int i1 = i0 + 8;
    const int jq = (lane & 3) * 2;                     // in-frag col pair base
    float* wrow0 = W ? W + ((size_t)bh * SEQ + i0) * SEQ : (float*)0;
    float* wrow1 = W ? W + ((size_t)bh * SEQ + i1) * SEQ : (float*)0;

    float o[16][4];
    #pragma unroll
    for (int n = 0; n < 16; ++n)
        #pragma unroll
        for (int r = 0; r < 4; ++r) o[n][r] = 0.0f;
    float rsum0 = 0.0f, rsum1 = 0.0f;
    const float SCALE = 0.08838834764831843f;

    // ldmatrix lane decomposition
    const int lt = lane >> 3, lr = lane & 7;

    const int nkt = 2 * qt + 2;
    for (int kt = 0; kt < nkt; ++kt) {
        __syncthreads();   // previous iteration's reads done before overwriting K/V

        // ---- Load K/V tile -> smem hi/lo ----
        const float* Kt = K + base + (size_t)kt * BN * DH;
        const float* Vt = V + base + (size_t)kt * BN * DH;
        #pragma unroll
        for (int e = tid; e < BN * DH / 4; e += NT) {
            int row = e >> 5, c4 = (e & 31) * 4;
            split4_store(sm + E_KHI, sm + E_KLO, row * STR + c4,
                         *(const float4*)&Kt[row * DH + c4]);
            split4_store(sm + E_VHI, sm + E_VLO, row * STR + c4,
                         *(const float4*)&Vt[row * DH + c4]);
        }
        __syncthreads();

        // ---- QK: S[64x32] via 3-term bf16 emulation ----
        float S[4][4];
        #pragma unroll
        for (int n = 0; n < 4; ++n)
            #pragma unroll
            for (int r = 0; r < 4; ++r) S[n][r] = 0.0f;

        #pragma unroll
        for (int ks = 0; ks < 8; ++ks) {
            const int k0 = ks * 16;
            uint32_t a_off = (uint32_t)((wid * 16 + (lt & 1) * 8 + lr) * STR
                                        + k0 + (lt >> 1) * 8);
            uint32_t ah[4], al[4];
            ldsm4(ah, sb + (E_QHI + a_off) * 2);
            ldsm4(al, sb + (E_QLO + a_off) * 2);
            #pragma unroll
            for (int p = 0; p < 2; ++p) {
                uint32_t b_off = (uint32_t)((p * 16 + (lt >> 1) * 8 + lr) * STR
                                            + k0 + (lt & 1) * 8);
                uint32_t bhr[4], blr[4];
                ldsm4(bhr, sb + (E_KHI + b_off) * 2);
                ldsm4(blr, sb + (E_KLO + b_off) * 2);
                mma16816(S[2*p],   ah, bhr[0], bhr[1]);
                mma16816(S[2*p],   ah, blr[0], blr[1]);
                mma16816(S[2*p],   al, bhr[0], bhr[1]);
                mma16816(S[2*p+1], ah, bhr[2], bhr[3]);
                mma16816(S[2*p+1], ah, blr[2], blr[3]);
                mma16816(S[2*p+1], al, bhr[2], bhr[3]);
            }
        }

        // ---- exp + causal mask + W store (unnormalized), in registers ----
        #pragma unroll
        for (int nf = 0; nf < 4; ++nf) {
            const int j0 = kt * BN + nf * 8 + jq;
            float p0 = (j0     <= i0) ? __expf(fmaf(S[nf][0], SCALE, -12.0f)) : 0.0f;
            float p1 = (j0 + 1 <= i0) ? __expf(fmaf(S[nf][1], SCALE, -12.0f)) : 0.0f;
            float p2 = (j0     <= i1) ? __expf(fmaf(S[nf][2], SCALE, -12.0f)) : 0.0f;
            float p3 = (j0 + 1 <= i1) ? __expf(fmaf(S[nf][3], SCALE, -12.0f)) : 0.0f;
            rsum0 += p0 + p1;
            rsum1 += p2 + p3;
            if (wrow0) {
                *(float2*)(wrow0 + j0) = make_float2(p0, p1);
                *(float2*)(wrow1 + j0) = make_float2(p2, p3);
            }
            S[nf][0] = p0; S[nf][1] = p1; S[nf][2] = p2; S[nf][3] = p3;
        }

        // ---- PV: O += P * V (3-term bf16 emulation), P from registers ----
        #pragma unroll
        for (int kk = 0; kk < 2; ++kk) {
            uint32_t pah[4], pal[4];
            pah[0] = bpackf(S[2*kk][0],   S[2*kk][1]);
            pah[1] = bpackf(S[2*kk][2],   S[2*kk][3]);
            pah[2] = bpackf(S[2*kk+1][0], S[2*kk+1][1]);
            pah[3] = bpackf(S[2*kk+1][2], S[2*kk+1][3]);
            pal[0] = bpackres(S[2*kk][0],   S[2*kk][1]);
            pal[1] = bpackres(S[2*kk][2],   S[2*kk][3]);
            pal[2] = bpackres(S[2*kk+1][0], S[2*kk+1][1]);
            pal[3] = bpackres(S[2*kk+1][2], S[2*kk+1][3]);
            #pragma unroll
            for (int np = 0; np < 8; ++np) {
                uint32_t v_off = (uint32_t)((kk * 16 + (lt & 1) * 8 + lr) * STR
                                            + np * 16 + (lt >> 1) * 8);
                uint32_t vh[4], vl[4];
                ldsm4t(vh, sb + (E_VHI + v_off) * 2);
                ldsm4t(vl, sb + (E_VLO + v_off) * 2);
                mma16816(o[2*np],   pah, vh[0], vh[1]);
                mma16816(o[2*np],   pah, vl[0], vl[1]);
                mma16816(o[2*np],   pal, vh[0], vh[1]);
                mma16816(o[2*np+1], pah, vh[2], vh[3]);
                mma16816(o[2*np+1], pah, vl[2], vl[3]);
                mma16816(o[2*np+1], pal, vh[2], vh[3]);
            }
        }
    }

    // ---- row-sum reduce across quad lanes ----
    rsum0 += __shfl_xor_sync(0xffffffffu, rsum0, 1);
    rsum0 += __shfl_xor_sync(0xffffffffu, rsum0, 2);
    rsum1 += __shfl_xor_sync(0xffffffffu, rsum1, 1);
    rsum1 += __shfl_xor_sync(0xffffffffu, rsum1, 2);
    const float rinv0 = 1.0f / rsum0;
    const float rinv1 = 1.0f / rsum1;
    if ((lane & 3) == 0) {
        g_rls[bh * SEQ + i0] = rinv0;
        g_rls[bh * SEQ + i1] = rinv1;
    }

    // ---- context out ----
    if (Ctx) {
        float* c0 = Ctx + ((size_t)bh * SEQ + i0) * DH;
        float* c1 = Ctx + ((size_t)bh * SEQ + i1) * DH;
        #pragma unroll
        for (int nf = 0; nf < 16; ++nf) {
            const int cc = nf * 8 + jq;
            *(float2*)(c0 + cc) = make_float2(o[nf][0] * rinv0, o[nf][1] * rinv0);
            *(float2*)(c1 + cc) = make_float2(o[nf][2] * rinv1, o[nf][3] * rinv1);
        }
    }
}

// Pass 2: scale causal region by 1/rowsum, zero strictly-upper region.
__global__ void __launch_bounds__(256)
scale_w(float* __restrict__ Wt)
{
    const int row = blockIdx.x;
    const int bh  = blockIdx.y;
    const float rinv = g_rls[bh * SEQ + row];
    float* wr = Wt + ((size_t)bh * SEQ + row) * SEQ;

    int c0 = threadIdx.x * 4;
    #pragma unroll
    for (int it = 0; it < 2; ++it, c0 += 1024) {
        if (c0 > row) {
            *(float4*)&wr[c0] = make_float4(0.f, 0.f, 0.f, 0.f);
        } else {
            float4 w = *(const float4*)&wr[c0];
            w.x = w.x * rinv;
            w.y = (c0 + 1 <= row) ? w.y * rinv : 0.0f;
            w.z = (c0 + 2 <= row) ? w.z * rinv : 0.0f;
            w.w = (c0 + 3 <= row) ? w.w * rinv : 0.0f;
            *(float4*)&wr[c0] = w;
        }
    }
}

extern "C" void kernel_launch(void* const* d_in, const int* in_sizes, int n_in,
                              void* d_out, int out_size)
{
    const float* q = (const float*)d_in[0];
    const float* k = (const float*)d_in[1];
    const float* v = (const float*)d_in[2];

    const long long CTX_E = (long long)NBH * SEQ * DH;
    const long long W_E   = (long long)NBH * SEQ * SEQ;

    float* ctx = 0;
    float* w   = 0;
    const long long os = (long long)out_size;
    if (os == CTX_E + W_E)      { ctx = (float*)d_out; w = (float*)d_out + CTX_E; }
    else if (os == CTX_E)       { ctx = (float*)d_out; }
    else if (os == W_E)         { w   = (float*)d_out; }
    else                        { ctx = (float*)d_out; }

    cudaFuncSetAttribute(attn_mma,
                         cudaFuncAttributeMaxDynamicSharedMemorySize, SM_BYTES);

    dim3 grid1(QTILES, NBH);
    attn_mma<<<grid1, NT, SM_BYTES>>>(q, k, v, w, ctx);

    if (w) {
        dim3 grid2(SEQ, NBH);
        scale_w<<<grid2, 256>>>(w);
    }
}